// round 10
// baseline (speedup 1.0000x reference)
#include <cuda_runtime.h>

// Scratch (no device allocation allowed -> __device__ globals)
__device__ float g_part[1024 * 2]; // partial maxes [B*16, C]
__device__ float g_M[2 * 64];      // fused weights W1@W2        [C, D2]
__device__ float g_c[64 * 64];     // per-batch fused bias       [B, D2]
__device__ int   g_s1a = 0, g_s1b = 0;   // sync-1 counters (self-resetting)
__device__ int   g_s2a = 0, g_s2b = 0;   // sync-2 counters (self-resetting)

static const int B_ = 64;
static const int N_ = 32768;
static const int GRID = 1036;            // 7 per SM * 148; capacity is 8/SM at
                                         // 32 regs -> co-residency guaranteed
static const int P1_BLOCKS = 1024;       // 16 chunks per batch
static const int VBLOCKS = B_ * N_ / 64; // 32768 virtual main blocks

// Software grid barrier. Safe because the whole grid is co-resident:
// 1036 blocks < 148 SMs * 8 blocks/SM capacity (launch bounds force
// <=32 regs, 256 thr/block, ~0 smem). Counters self-reset: the last
// block through the second counter zeroes both, so graph replays start
// from a clean state.
__device__ __forceinline__ void grid_sync(int* ca, int* cb) {
    __syncthreads();
    __threadfence();
    if (threadIdx.x == 0) {
        atomicAdd(ca, 1);
        while (atomicAdd(ca, 0) < GRID) { __nanosleep(64); }
        int t = atomicAdd(cb, 1);
        if (t == GRID - 1) {
            atomicExch(cb, 0);
            atomicExch(ca, 0);
        }
    }
    __syncthreads();
    __threadfence();
}

__global__ void __launch_bounds__(256, 8)
fused_kernel(const float4* __restrict__ x4,
             const float2* __restrict__ x2,
             const float*  __restrict__ W1,
             const float*  __restrict__ b1,
             const float*  __restrict__ G1,
             const float*  __restrict__ W2,
             const float*  __restrict__ b2,
             float4* __restrict__ out) {
    const int tid = threadIdx.x;
    const int blk = blockIdx.x;

    // ---------------- Phase 1: partial per-batch max (blocks 0..1023) ------
    if (blk < P1_BLOCKS) {
        const long long base = (long long)blk * 1024;  // float4 index
        const float NEG_INF = __int_as_float(0xff800000);
        float m0 = NEG_INF, m1 = NEG_INF;
        #pragma unroll
        for (int j = 0; j < 4; j++) {
            float4 v = __ldg(&x4[base + j * 256 + tid]);
            m0 = fmaxf(m0, fmaxf(v.x, v.z));
            m1 = fmaxf(m1, fmaxf(v.y, v.w));
        }
        #pragma unroll
        for (int o = 16; o > 0; o >>= 1) {
            m0 = fmaxf(m0, __shfl_xor_sync(0xffffffffu, m0, o));
            m1 = fmaxf(m1, __shfl_xor_sync(0xffffffffu, m1, o));
        }
        __shared__ float s0[8], s1[8];
        const int lane = tid & 31;
        const int w    = tid >> 5;
        if (lane == 0) { s0[w] = m0; s1[w] = m1; }
        __syncthreads();
        if (tid == 0) {
            float r0 = s0[0], r1 = s1[0];
            #pragma unroll
            for (int j = 1; j < 8; j++) {
                r0 = fmaxf(r0, s0[j]);
                r1 = fmaxf(r1, s1[j]);
            }
            g_part[blk * 2 + 0] = r0;
            g_part[blk * 2 + 1] = r1;
        }
    }

    grid_sync(&g_s1a, &g_s1b);

    // ---------------- Phase 1.5: prep (blocks 0..64, threads 0..63) --------
    // Low-register variant: one output column per thread.
    if (blk < 64 && tid < 64) {
        const int d = tid;
        float beta0 = __int_as_float(0xff800000);
        float beta1 = beta0;
        #pragma unroll
        for (int j = 0; j < 16; j++) {
            beta0 = fmaxf(beta0, g_part[(blk * 16 + j) * 2 + 0]);
            beta1 = fmaxf(beta1, g_part[(blk * 16 + j) * 2 + 1]);
        }
        float acc = b2[d];
        #pragma unroll
        for (int k = 0; k < 32; k++) {
            const float wgt = b1[k] - beta0 * G1[k] - beta1 * G1[32 + k];
            acc = fmaf(wgt, W2[k * 64 + d], acc);
        }
        g_c[blk * 64 + d] = acc;
    } else if (blk == 64 && tid < 64) {
        const int d = tid;
        float a0 = 0.f, a1 = 0.f;
        #pragma unroll
        for (int k = 0; k < 32; k++) {
            const float w2kd = W2[k * 64 + d];
            a0 = fmaf(W1[k],      w2kd, a0);
            a1 = fmaf(W1[32 + k], w2kd, a1);
        }
        g_M[d]      = a0;
        g_M[64 + d] = a1;
    }

    grid_sync(&g_s2a, &g_s2b);

    // ---------------- Phase 2: streaming epilogue --------------------------
    // Virtual block v = 64 points in one batch (64 | 32768); thread writes
    // 4 float4 with streaming (evict-first) stores — the proven 32-reg shape.
    const int d4 = tid & 15;
    const int pl = tid >> 4;
    const float4 m0 = ((const float4*)g_M)[d4];
    const float4 m1 = ((const float4*)g_M)[16 + d4];

    for (int v = blk; v < VBLOCKS; v += GRID) {
        const int b = v >> 9;  // 512 virtual blocks per batch
        const float4 cc = ((const float4*)g_c)[b * 16 + d4];

        const long long p0    = (long long)v * 64 + pl;
        const long long obase = (long long)v * 1024 + tid;

        float2 xv[4];
        #pragma unroll
        for (int j = 0; j < 4; j++)
            xv[j] = __ldg(&x2[p0 + j * 16]);

        #pragma unroll
        for (int j = 0; j < 4; j++) {
            float4 o;
            o.x = fmaf(xv[j].x, m0.x, fmaf(xv[j].y, m1.x, cc.x));
            o.y = fmaf(xv[j].x, m0.y, fmaf(xv[j].y, m1.y, cc.y));
            o.z = fmaf(xv[j].x, m0.z, fmaf(xv[j].y, m1.z, cc.z));
            o.w = fmaf(xv[j].x, m0.w, fmaf(xv[j].y, m1.w, cc.w));
            __stcs(&out[obase + j * 256], o);
        }
    }
}

extern "C" void kernel_launch(void* const* d_in, const int* in_sizes, int n_in,
                              void* d_out, int out_size) {
    const float* pd = (const float*)d_in[0];   // [64, 32768, 2]
    const float* W1 = (const float*)d_in[1];   // [2, 32]
    const float* b1 = (const float*)d_in[2];   // [32]
    const float* G1 = (const float*)d_in[3];   // [2, 32]
    const float* W2 = (const float*)d_in[4];   // [32, 64]
    const float* b2 = (const float*)d_in[5];   // [64]
    float* out = (float*)d_out;                // [64, 32768, 64]

    fused_kernel<<<GRID, 256>>>((const float4*)pd, (const float2*)pd,
                                W1, b1, G1, W2, b2, (float4*)out);
}

// round 11
// speedup vs baseline: 1.0243x; 1.0243x over previous
#include <cuda_runtime.h>

// Scratch (no device allocation allowed -> __device__ globals)
__device__ float g_part[1024 * 2];       // partial maxes [B*16, C]
__device__ float g_M[2 * 64];            // fused weights W1@W2   [C, D2]
__device__ float g_c[64 * 64];           // per-batch fused bias  [B, D2]
__device__ int   g_bcnt[64];             // per-batch chunk tickets (self-reset)
__device__ int   g_scnt[64];             // per-batch store tickets (self-reset)
__device__ volatile int g_flag[64];      // per-batch ready flags  (self-reset)

static const int B_ = 64;
static const int N_ = 32768;
static const int P1_BLOCKS = 1024;       // 16 chunks per batch, bids 0..1023
static const int STORE_BLOCKS = B_ * N_ / 64;  // 32768, bids 1024..

// Single launch, two block roles, per-batch flag handoff.
// Deadlock-free: launch bounds force <=32 regs -> 8 blocks/SM -> wave-1
// capacity 148*8=1184 >= 1024, so every chunk block (bids 0..1023) is
// resident before any store block can starve waiting on its flag.
__global__ void __launch_bounds__(256, 8)
fused_kernel(const float4* __restrict__ x4,
             const float2* __restrict__ x2,
             const float*  __restrict__ W1,
             const float*  __restrict__ b1,
             const float*  __restrict__ G1,
             const float*  __restrict__ W2,
             const float*  __restrict__ b2,
             float4* __restrict__ out) {
    const int tid = threadIdx.x;
    const int blk = blockIdx.x;
    const float NEG_INF = __int_as_float(0xff800000);

    if (blk < P1_BLOCKS) {
        // ================= chunk role: partial max over 16KB ===============
        const int bb = blk >> 4;                       // batch of this chunk
        {
            const long long base = (long long)blk * 1024;  // float4 index
            float m0 = NEG_INF, m1 = NEG_INF;
            #pragma unroll
            for (int j = 0; j < 4; j++) {
                float4 v = __ldg(&x4[base + j * 256 + tid]);
                m0 = fmaxf(m0, fmaxf(v.x, v.z));
                m1 = fmaxf(m1, fmaxf(v.y, v.w));
            }
            #pragma unroll
            for (int o = 16; o > 0; o >>= 1) {
                m0 = fmaxf(m0, __shfl_xor_sync(0xffffffffu, m0, o));
                m1 = fmaxf(m1, __shfl_xor_sync(0xffffffffu, m1, o));
            }
            __shared__ float s0[8], s1[8];
            const int lane = tid & 31;
            const int w    = tid >> 5;
            if (lane == 0) { s0[w] = m0; s1[w] = m1; }
            __syncthreads();
            if (tid == 0) {
                float r0 = s0[0], r1 = s1[0];
                #pragma unroll
                for (int j = 1; j < 8; j++) {
                    r0 = fmaxf(r0, s0[j]);
                    r1 = fmaxf(r1, s1[j]);
                }
                g_part[blk * 2 + 0] = r0;
                g_part[blk * 2 + 1] = r1;
            }
        }

        // ---- last chunk of this batch becomes the finisher ----
        __shared__ int isLast;
        __threadfence();
        if (tid == 0) {
            int t = atomicAdd(&g_bcnt[bb], 1);
            isLast = (t == 15);
            if (isLast) atomicExch(&g_bcnt[bb], 0);   // reset for next replay
        }
        __syncthreads();
        if (!isLast) return;

        // final 16-way max for this batch -> shared
        __shared__ float sb0, sb1;
        if (tid < 32) {
            const int ch = tid & 1;
            const int j  = tid >> 1;          // 0..15
            float m = (tid < 32) ? g_part[(bb * 16 + j) * 2 + ch] : NEG_INF;
            #pragma unroll
            for (int o = 16; o >= 2; o >>= 1)
                m = fmaxf(m, __shfl_xor_sync(0xffffffffu, m, o));
            if (tid == 0) sb0 = m;
            if (tid == 1) sb1 = m;
        }
        __syncthreads();
        const float beta0 = sb0;
        const float beta1 = sb1;

        // c[bb, d] for d = tid (threads 0..63); M redundantly (threads 64..127,
        // all finishers write bit-identical values -> benign race).
        if (tid < 64) {
            const int d = tid;
            float acc = b2[d];
            #pragma unroll
            for (int k = 0; k < 32; k++) {
                const float wgt = b1[k] - beta0 * G1[k] - beta1 * G1[32 + k];
                acc = fmaf(wgt, W2[k * 64 + d], acc);
            }
            g_c[bb * 64 + d] = acc;
        } else if (tid < 128) {
            const int d = tid - 64;
            float a0 = 0.f, a1 = 0.f;
            #pragma unroll
            for (int k = 0; k < 32; k++) {
                const float w2kd = W2[k * 64 + d];
                a0 = fmaf(W1[k],      w2kd, a0);
                a1 = fmaf(W1[32 + k], w2kd, a1);
            }
            g_M[d]      = a0;
            g_M[64 + d] = a1;
        }
        __syncthreads();
        __threadfence();
        if (tid == 0) g_flag[bb] = 1;     // release: c[bb] and M visible
        return;
    }

    // ================= store role: out[p,:] = x[p,:]@M + c[b,:] ============
    const int v  = blk - P1_BLOCKS;       // 0..32767, 64 points each
    const int b  = v >> 9;                // 512 store blocks per batch

    // wait for this batch's c (and M) to be published
    if (tid == 0) {
        while (g_flag[b] == 0) { __nanosleep(128); }
        // ticket for flag reset; all 512 incremented => all passed the spin
        int t = atomicAdd(&g_scnt[b], 1);
        if (t == STORE_BLOCKS / B_ - 1) {   // last store block of this batch
            atomicExch(&g_scnt[b], 0);
            g_flag[b] = 0;                  // reset for next replay
        }
    }
    __syncthreads();
    __threadfence();

    const int d4 = tid & 15;
    const int pl = tid >> 4;
    const float4 m0 = ((const float4*)g_M)[d4];
    const float4 m1 = ((const float4*)g_M)[16 + d4];
    const float4 cc = ((const float4*)g_c)[b * 16 + d4];

    const long long p0    = (long long)v * 64 + pl;
    const long long obase = (long long)v * 1024 + tid;

    float2 xv[4];
    #pragma unroll
    for (int j = 0; j < 4; j++)
        xv[j] = __ldg(&x2[p0 + j * 16]);

    #pragma unroll
    for (int j = 0; j < 4; j++) {
        float4 o;
        o.x = fmaf(xv[j].x, m0.x, fmaf(xv[j].y, m1.x, cc.x));
        o.y = fmaf(xv[j].x, m0.y, fmaf(xv[j].y, m1.y, cc.y));
        o.z = fmaf(xv[j].x, m0.z, fmaf(xv[j].y, m1.z, cc.z));
        o.w = fmaf(xv[j].x, m0.w, fmaf(xv[j].y, m1.w, cc.w));
        __stcs(&out[obase + j * 256], o);
    }
}

extern "C" void kernel_launch(void* const* d_in, const int* in_sizes, int n_in,
                              void* d_out, int out_size) {
    const float* pd = (const float*)d_in[0];   // [64, 32768, 2]
    const float* W1 = (const float*)d_in[1];   // [2, 32]
    const float* b1 = (const float*)d_in[2];   // [32]
    const float* G1 = (const float*)d_in[3];   // [2, 32]
    const float* W2 = (const float*)d_in[4];   // [32, 64]
    const float* b2 = (const float*)d_in[5];   // [64]
    float* out = (float*)d_out;                // [64, 32768, 64]

    fused_kernel<<<P1_BLOCKS + STORE_BLOCKS, 256>>>(
        (const float4*)pd, (const float2*)pd, W1, b1, G1, W2, b2, (float4*)out);
}